// round 1
// baseline (speedup 1.0000x reference)
#include <cuda_runtime.h>
#include <cuda_bf16.h>

// TELIF: temporal-encoded LIF neuron scan.
//   tx : [T, B, N] float32   (T=512, B=64, N=1024)
//   TE : [N, T]    float32
//   out: [T, B, N] float32 spikes
//
// Recurrence per (b, n), sequential in t:
//   th = th + v*TE[n,t] - (th - THRESHOLD)*BETA
//   v  = v*DECAY*(1 - y) + x
//   y  = (v > th) ? 1 : 0

#define T_STEPS 512
#define B_DIM   64
#define N_DIM   1024
#define BN      (B_DIM * N_DIM)      // 65536
#define UNROLL  8

#define REST      0.0f
#define DECAY     0.2f
#define THRESHOLD 0.3f
#define BETA      0.02f

// Transposed temporal encoding: TEt[t][n]  (2 MB static device scratch)
__device__ float g_TEt[T_STEPS * N_DIM];

// ---------------------------------------------------------------------------
// Pre-pass: transpose TE [N, T] -> g_TEt [T, N] via shared-memory tiles.
// Grid: (T/32, N/32) = (16, 32), block (32, 8).
// ---------------------------------------------------------------------------
__global__ void transpose_te_kernel(const float* __restrict__ TE) {
    __shared__ float tile[32][33];
    const int tbase = blockIdx.x * 32;   // t tile origin
    const int nbase = blockIdx.y * 32;   // n tile origin

    #pragma unroll
    for (int r = threadIdx.y; r < 32; r += 8) {
        // coalesced read along t
        tile[r][threadIdx.x] = TE[(nbase + r) * T_STEPS + tbase + threadIdx.x];
    }
    __syncthreads();
    #pragma unroll
    for (int r = threadIdx.y; r < 32; r += 8) {
        // coalesced write along n
        g_TEt[(tbase + r) * N_DIM + nbase + threadIdx.x] = tile[threadIdx.x][r];
    }
}

// ---------------------------------------------------------------------------
// Main scan: one thread per (b, n). Double-buffered register prefetch of
// UNROLL timesteps of tx and TEt so ~16 independent 128B loads/warp are in
// flight while the (serial) recurrence math runs.
// ---------------------------------------------------------------------------
__global__ void __launch_bounds__(128) telif_kernel(
    const float* __restrict__ tx,
    float* __restrict__ ty)
{
    const int g = blockIdx.x * blockDim.x + threadIdx.x;  // g = b*N + n
    const int n = g & (N_DIM - 1);

    float v  = REST;
    float y  = 0.0f;
    float th = THRESHOLD;

    float xb[2][UNROLL];
    float tb[2][UNROLL];

    // prologue: prefetch chunk 0
    #pragma unroll
    for (int u = 0; u < UNROLL; u++) {
        xb[0][u] = tx[u * BN + g];
        tb[0][u] = g_TEt[u * N_DIM + n];
    }

    int buf = 0;
    for (int tc = 0; tc < T_STEPS; tc += UNROLL) {
        const int nb = buf ^ 1;
        // prefetch next chunk (independent of recurrence state)
        if (tc + UNROLL < T_STEPS) {
            #pragma unroll
            for (int u = 0; u < UNROLL; u++) {
                xb[nb][u] = tx[(tc + UNROLL + u) * BN + g];
                tb[nb][u] = g_TEt[(tc + UNROLL + u) * N_DIM + n];
            }
        }
        // compute current chunk
        #pragma unroll
        for (int u = 0; u < UNROLL; u++) {
            const float x  = xb[buf][u];
            const float te = tb[buf][u];
            th = th + v * te - (th - THRESHOLD) * BETA;
            v  = v * DECAY * (1.0f - y) + x;
            y  = (v > th) ? 1.0f : 0.0f;
            ty[(tc + u) * BN + g] = y;
        }
        buf = nb;
    }
}

// ---------------------------------------------------------------------------
extern "C" void kernel_launch(void* const* d_in, const int* in_sizes, int n_in,
                              void* d_out, int out_size) {
    const float* tx = (const float*)d_in[0];   // [T, B, N]
    const float* TE = (const float*)d_in[1];   // [N, T]
    float* ty = (float*)d_out;                 // [T, B, N]
    (void)in_sizes; (void)n_in; (void)out_size;

    dim3 tgrid(T_STEPS / 32, N_DIM / 32);
    dim3 tblock(32, 8);
    transpose_te_kernel<<<tgrid, tblock>>>(TE);

    telif_kernel<<<BN / 128, 128>>>(tx, ty);
}